// round 8
// baseline (speedup 1.0000x reference)
#include <cuda_runtime.h>
#include <cuda_fp16.h>

#define CH 256     // B*C channels
#define HH 251
#define WW 509
#define HP 256
#define WP 512

// scratch: per channel, layout [seg][w][hL], seg=h>>3 (32), w (512), hL=h&7 (8)
__device__ __align__(16) __half2 g_A[(size_t)CH * WP * HP];   // 128 MB

__device__ __forceinline__ float2 cmul(float2 a, float2 b) {
    return make_float2(fmaf(a.x, b.x, -a.y * b.y),
                       fmaf(a.x, b.y,  a.y * b.x));
}

// bit-reverse of a compile-time-constant index (folds under #pragma unroll)
__device__ __forceinline__ int crev(int x, int bits) {
    int r = 0;
    #pragma unroll
    for (int i = 0; i < 5; ++i)
        if (i < bits) r |= ((x >> i) & 1) << (bits - 1 - i);
    return r;
}

// 16-point DIF FFT in registers. Input natural order; output v[r] = X[crev(r,4)].
// j==4 twiddle is an exact ±i rotation (free swap), j==0 a copy.
template<bool INV>
__device__ __forceinline__ void reg_fft16(float2* v) {
    const float C[8] = { 1.f,  0.9238795325112867f,  0.7071067811865476f,  0.3826834323650898f,
                         0.f, -0.3826834323650898f, -0.7071067811865476f, -0.9238795325112867f};
    const float S[8] = { 0.f, -0.3826834323650898f, -0.7071067811865476f, -0.9238795325112867f,
                        -1.f, -0.9238795325112867f, -0.7071067811865476f, -0.3826834323650898f};
    #pragma unroll
    for (int m = 8; m >= 1; m >>= 1) {
        #pragma unroll
        for (int b = 0; b < 16; b += 2 * m) {
            #pragma unroll
            for (int i = 0; i < m; ++i) {
                float2 lo = v[b + i], hi = v[b + i + m];
                v[b + i] = make_float2(lo.x + hi.x, lo.y + hi.y);
                float2 d = make_float2(lo.x - hi.x, lo.y - hi.y);
                const int j = i * (8 / m);
                if (j == 0) {
                    v[b + i + m] = d;
                } else if (j == 4) {
                    v[b + i + m] = INV ? make_float2(-d.y, d.x)
                                       : make_float2( d.y, -d.x);
                } else {
                    float2 wt = make_float2(C[j], INV ? -S[j] : S[j]);
                    v[b + i + m] = cmul(d, wt);
                }
            }
        }
    }
}

// twiddle: v[slot holding k1=c] *= W_N^{+/- t*c}. Log-depth power groups.
template<bool INV>
__device__ __forceinline__ void twiddle16_nat(float2* v, int t, float twoPiOverN) {
    float ang = (INV ? twoPiOverN : -twoPiOverN) * (float)t;
    float2 w1; __sincosf(ang, &w1.y, &w1.x);
    float2 w2 = cmul(w1, w1);
    float2 w3 = cmul(w1, w2);
    float2 W4 = cmul(w2, w2);
    v[crev(1, 4)] = cmul(v[crev(1, 4)], w1);
    v[crev(2, 4)] = cmul(v[crev(2, 4)], w2);
    v[crev(3, 4)] = cmul(v[crev(3, 4)], w3);
    float2 Q = W4;
    #pragma unroll
    for (int g = 1; g < 4; ++g) {
        float2 q1 = cmul(Q, w1), q2 = cmul(Q, w2), q3 = cmul(Q, w3);
        v[crev(4 * g + 0, 4)] = cmul(v[crev(4 * g + 0, 4)], Q);
        v[crev(4 * g + 1, 4)] = cmul(v[crev(4 * g + 1, 4)], q1);
        v[crev(4 * g + 2, 4)] = cmul(v[crev(4 * g + 2, 4)], q2);
        v[crev(4 * g + 3, 4)] = cmul(v[crev(4 * g + 3, 4)], q3);
        if (g < 3) Q = cmul(Q, W4);
    }
}

// K1: rows. z = u + i*k (zero padded), FFT-512 (16reg x [16reg x 2-fold]),
// fp16 store into [seg][w][hL] -> 16KB fully contiguous per block.
__global__ void __launch_bounds__(256) fftconv_k1(const float* __restrict__ u,
                                                  const float* __restrict__ kk) {
    __shared__ __align__(16) float2 S[8][16][33];
    const int tid = threadIdx.x;
    const int lane = tid & 31, wid = tid >> 5;
    const int c = blockIdx.y;
    const int seg = blockIdx.x;
    const int h = seg * 8 + wid;

    float2 v[16];
    if (h < HH) {
        const float* pu = u + (size_t)(c * HH + h) * WW;
        const float* pk = kk + (size_t)(c * HH + h) * WW;
        #pragma unroll
        for (int s = 0; s < 16; ++s) {
            int n = lane + 32 * s;
            bool ok = n < WW;
            v[s].x = ok ? pu[n] : 0.f;
            v[s].y = ok ? pk[n] : 0.f;
        }
    } else {
        #pragma unroll
        for (int s = 0; s < 16; ++s) v[s] = make_float2(0.f, 0.f);
    }

    reg_fft16<false>(v);
    twiddle16_nat<false>(v, lane, 0.012271846303085130f);   // W512^{t*k1}
    #pragma unroll
    for (int r = 0; r < 16; ++r) S[wid][crev(r, 4)][lane] = v[r];
    __syncwarp();

    const int k1 = lane & 15, k2 = lane >> 4;
    {
        float2 q1; __sincosf(-0.19634954084936207f * (float)k2, &q1.y, &q1.x);
        float2 q2 = cmul(q1, q1);
        float2 q3 = cmul(q1, q2);
        float2 Q4 = cmul(q2, q2);
        float2 Qg = make_float2(1.f, 0.f);
        const float sgn = k2 ? -1.f : 1.f;
        #pragma unroll
        for (int g = 0; g < 4; ++g) {
            float2 t1 = cmul(Qg, q1), t2 = cmul(Qg, q2), t3 = cmul(Qg, q3);
            #pragma unroll
            for (int r = 0; r < 4; ++r) {
                int a = 4 * g + r;
                float2 L0 = S[wid][k1][a];
                float2 L1 = S[wid][k1][a + 16];
                float2 hh = make_float2(L0.x + sgn * L1.x, L0.y + sgn * L1.y);
                float2 wp_ = (r == 0) ? Qg : (r == 1) ? t1 : (r == 2) ? t2 : t3;
                v[a] = cmul(hh, wp_);
            }
            if (g < 3) Qg = cmul(Qg, Q4);
        }
    }
    reg_fft16<false>(v);                  // v[r] = X[lane + 32*crev(r)]
    __syncwarp();

    __half2* brow = (__half2*)&S[wid][0][0];
    #pragma unroll
    for (int r = 0; r < 16; ++r) {
        int k = lane + 32 * crev(r, 4);
        brow[k] = __floats2half2_rn(v[r].x, v[r].y);
    }
    __syncthreads();

    uint4* dst4 = (uint4*)(g_A + ((size_t)c * 32 + seg) * (512 * 8));
    #pragma unroll
    for (int q = 0; q < 4; ++q) {
        int li = tid + 256 * q;
        int w = li >> 1, part = li & 1;
        __half2 a0 = ((const __half2*)&S[part * 4 + 0][0][0])[w];
        __half2 a1 = ((const __half2*)&S[part * 4 + 1][0][0])[w];
        __half2 a2 = ((const __half2*)&S[part * 4 + 2][0][0])[w];
        __half2 a3 = ((const __half2*)&S[part * 4 + 3][0][0])[w];
        uint4 t;
        t.x = *reinterpret_cast<unsigned*>(&a0);
        t.y = *reinterpret_cast<unsigned*>(&a1);
        t.z = *reinterpret_cast<unsigned*>(&a2);
        t.w = *reinterpret_cast<unsigned*>(&a3);
        dst4[li] = t;
    }
}

// K2: column pair (w, 512-w): FFT-256 (16x16), Hermitian split, P=U*K * 2^-12,
// IFFT-256 + store for w<=256 only. Block-cooperative staging for coalescing.
__global__ void __launch_bounds__(256) fftconv_k2() {
    __shared__ __align__(16) char SM[34816];
    __half2* stage_in  = (__half2*)SM;
    float2*  Rbase     = (float2*)SM;
    __half2* stage_out = (__half2*)SM;
    const int tid = threadIdx.x;
    const int lane = tid & 31, wp = tid >> 5;
    const int half = lane >> 4, tl = lane & 15;
    const int c = 255 - blockIdx.y;
    const int w0 = blockIdx.x * 8;
    const int nc = (blockIdx.x == 32) ? 1 : 8;
    const bool valid = (wp < nc);
    const __half2* gch = g_A + (size_t)c * (32 * 512 * 8);

    #pragma unroll
    for (int side = 0; side < 2; ++side) {
        for (int g = tid; g < nc * 32; g += 256) {
            int seg, wi;
            if (nc == 8) { seg = g >> 3; wi = g & 7; } else { seg = g; wi = 0; }
            int col = w0 + wi;
            if (side) col = (512 - col) & 511;
            const uint4* src4 = (const uint4*)(gch + ((size_t)seg * 512 + col) * 8);
            uint4 t0 = src4[0], t1 = src4[1];
            uint4* d4 = (uint4*)(stage_in + ((side * 8 + wi) * 264 + seg * 8));
            d4[0] = t0; d4[1] = t1;
        }
    }
    __syncthreads();

    float2 v[16];
    if (valid) {
        const __half2* own = stage_in + (half * 8 + wp) * 264;
        #pragma unroll
        for (int s = 0; s < 16; ++s) v[s] = __half22float2(own[tl + 16 * s]);
    }
    __syncthreads();

    float2* T    = Rbase + (wp * 2 + half) * 272;
    float2* Zoth = Rbase + (wp * 2 + (half ^ 1)) * 272;
    float2 v2[16];
    if (valid) {
        reg_fft16<false>(v);
        twiddle16_nat<false>(v, tl, 0.024543692606170260f);
        #pragma unroll
        for (int r = 0; r < 16; ++r) T[crev(r, 4) * 17 + tl] = v[r];
        __syncwarp();
        #pragma unroll
        for (int j = 0; j < 16; ++j) v[j] = T[tl * 17 + j];
        reg_fft16<false>(v);
        __syncwarp();

        #pragma unroll
        for (int r = 0; r < 16; ++r) T[tl + 16 * crev(r, 4)] = v[r];
        __syncwarp();

        if (half == 0) {
            #pragma unroll
            for (int r = 0; r < 16; ++r) {
                int k = tl + 16 * crev(r, 4);
                int km = (HP - k) & (HP - 1);
                float2 z1 = v[r];
                float2 z2 = Zoth[km];
                float2 uf = make_float2(0.5f * (z1.x + z2.x),  0.5f * (z1.y - z2.y));
                float2 kf = make_float2(0.5f * (z1.y + z2.y), -0.5f * (z1.x - z2.x));
                v2[crev(r, 4)] = cmul(uf, kf);
            }
        }
        __syncwarp();

        if (half == 0) {
            reg_fft16<true>(v2);
            twiddle16_nat<true>(v2, tl, 0.024543692606170260f);
            #pragma unroll
            for (int r = 0; r < 16; ++r) T[crev(r, 4) * 17 + tl] = v2[r];
        }
        __syncwarp();
        if (half == 0) {
            #pragma unroll
            for (int j = 0; j < 16; ++j) v2[j] = T[tl * 17 + j];
            reg_fft16<true>(v2);
        }
    }
    __syncthreads();

    if (valid && half == 0) {
        const float SC2 = 0.000244140625f;    // 2^-12 prescale (fp16 range)
        #pragma unroll
        for (int r = 0; r < 16; ++r)
            stage_out[wp * 264 + tl + 16 * crev(r, 4)] =
                __floats2half2_rn(v2[r].x * SC2, v2[r].y * SC2);
    }
    __syncthreads();

    for (int g = tid; g < nc * 32; g += 256) {
        int seg, wi;
        if (nc == 8) { seg = g >> 3; wi = g & 7; } else { seg = g; wi = 0; }
        const uint4* s4 = (const uint4*)(stage_out + (wi * 264 + seg * 8));
        uint4 t0 = s4[0], t1 = s4[1];
        uint4* dst4 = (uint4*)((__half2*)gch + ((size_t)seg * 512 + w0 + wi) * 8);
        dst4[0] = t0; dst4[1] = t1;
    }
}

// K3: irfft rows. Load G(h, 0..256), pack Z[j]=E+iO (half-size trick),
// one complex IFFT-256 per row (16 threads/row), y[2n]=Re, y[2n+1]=Im.
// 16 rows (2 segs) per 256-thread block.
__global__ void __launch_bounds__(256) fftconv_k3(float* __restrict__ y) {
    __shared__ __align__(16) char SM[34816];
    __half2* Gs = (__half2*)SM;           // [row g][w], stride 264 half2 (16.9 KB)
    float2*  Tb = (float2*)SM;            // [group][272] float2 (34.8 KB, reused)
    const int tid = threadIdx.x;
    const int g = tid >> 4, tl = tid & 15;
    const int c = blockIdx.y;
    const int sp = blockIdx.x;            // segpair: rows 16*sp .. 16*sp+15
    const int h = sp * 16 + g;

    // load 2 segs' w=0..256 slices (contiguous uint4 runs)
    #pragma unroll
    for (int sl = 0; sl < 2; ++sl) {
        const uint4* src4 = (const uint4*)(g_A + ((size_t)c * 32 + 2 * sp + sl) * (512 * 8));
        for (int li = tid; li < 514; li += 256) {
            int w = li >> 1, part = li & 1;
            uint4 t = src4[li];
            int r0 = sl * 8 + part * 4;
            Gs[(r0 + 0) * 264 + w] = *reinterpret_cast<__half2*>(&t.x);
            Gs[(r0 + 1) * 264 + w] = *reinterpret_cast<__half2*>(&t.y);
            Gs[(r0 + 2) * 264 + w] = *reinterpret_cast<__half2*>(&t.z);
            Gs[(r0 + 3) * 264 + w] = *reinterpret_cast<__half2*>(&t.w);
        }
    }
    __syncthreads();

    // Z[j] = (G[j]+conj(G[256-j])) + i * e^{+2pi i j/512} (G[j]-conj(G[256-j]))
    // (factor 2 vs the exact split; cancels against half-size IFFT scaling)
    const float Ct[16] = { 1.f,  0.980785280403230f,  0.923879532511287f,  0.831469612302545f,
                           0.707106781186548f,  0.555570233019602f,  0.382683432365090f,  0.195090322016128f,
                           0.f, -0.195090322016128f, -0.382683432365090f, -0.555570233019602f,
                          -0.707106781186548f, -0.831469612302545f, -0.923879532511287f, -0.980785280403230f};
    const float St[16] = { 0.f,  0.195090322016128f,  0.382683432365090f,  0.555570233019602f,
                           0.707106781186548f,  0.831469612302545f,  0.923879532511287f,  0.980785280403230f,
                           1.f,  0.980785280403230f,  0.923879532511287f,  0.831469612302545f,
                           0.707106781186548f,  0.555570233019602f,  0.382683432365090f,  0.195090322016128f};
    float2 base;                           // e^{+2pi i tl/512}
    __sincosf(0.012271846303085130f * (float)tl, &base.y, &base.x);

    float2 v[16];
    const __half2* grow = Gs + g * 264;
    #pragma unroll
    for (int cc = 0; cc < 16; ++cc) {
        int j = tl + 16 * cc;              // 0..255
        float2 Gj = __half22float2(grow[j]);
        float2 Gm = __half22float2(grow[256 - j]);
        float2 A = make_float2(Gj.x + Gm.x, Gj.y - Gm.y);   // G[j]+conj(Gm)
        float2 D = make_float2(Gj.x - Gm.x, Gj.y + Gm.y);   // G[j]-conj(Gm)
        float2 tw = cmul(base, make_float2(Ct[cc], St[cc]));
        float2 P = cmul(tw, D);
        v[cc] = make_float2(A.x - P.y, A.y + P.x);          // A + i*P
    }
    __syncthreads();                       // Gs dead; Tb live

    // inverse FFT-256 (16x16): input natural j=tl+16c, output z[tl+16*crev(r)]
    reg_fft16<true>(v);
    twiddle16_nat<true>(v, tl, 0.024543692606170260f);
    float2* T = Tb + g * 272;
    #pragma unroll
    for (int r = 0; r < 16; ++r) T[crev(r, 4) * 17 + tl] = v[r];
    __syncwarp();
    #pragma unroll
    for (int j = 0; j < 16; ++j) v[j] = T[tl * 17 + j];
    reg_fft16<true>(v);                    // v[r] = z[m], m = tl + 16*crev(r)

    if (h < HH) {
        const float s = 8.6316745750903e-05f;   // 2^-13.5
        float* py = y + (size_t)(c * HH + h) * WW;
        #pragma unroll
        for (int r = 0; r < 16; ++r) {
            int m = tl + 16 * crev(r, 4);       // y[2m]=Re, y[2m+1]=Im
            if (m <= 253) {
                py[2 * m]     = v[r].x * s;
                py[2 * m + 1] = v[r].y * s;
            } else if (m == 254) {
                py[508] = v[r].x * s;
            }
        }
    }
}

extern "C" void kernel_launch(void* const* d_in, const int* in_sizes, int n_in,
                              void* d_out, int out_size) {
    const float* u = (const float*)d_in[0];
    const float* k = (const float*)d_in[1];
    float* y = (float*)d_out;

    fftconv_k1<<<dim3(32, CH), 256>>>(u, k);     // seg 0..31 per channel
    fftconv_k2<<<dim3(33, CH), 256>>>();         // 257 column pairs, 8/block
    fftconv_k3<<<dim3(16, CH), 256>>>(y);        // 16 rows (2 segs) per block
}

// round 9
// speedup vs baseline: 1.0202x; 1.0202x over previous
#include <cuda_runtime.h>
#include <cuda_fp16.h>

#define CH 256     // B*C channels
#define HH 251
#define WW 509
#define HP 256
#define WP 512

// scratch: per channel, layout [seg][w][hL], seg=h>>3 (32), w (512), hL=h&7 (8)
__device__ __align__(16) __half2 g_A[(size_t)CH * WP * HP];   // 128 MB

__device__ __forceinline__ float2 cmul(float2 a, float2 b) {
    return make_float2(fmaf(a.x, b.x, -a.y * b.y),
                       fmaf(a.x, b.y,  a.y * b.x));
}

// bit-reverse of a compile-time-constant index (folds under #pragma unroll)
__device__ __forceinline__ int crev(int x, int bits) {
    int r = 0;
    #pragma unroll
    for (int i = 0; i < 5; ++i)
        if (i < bits) r |= ((x >> i) & 1) << (bits - 1 - i);
    return r;
}

// 16-point DIF FFT in registers. Input natural order; output v[r] = X[crev(r,4)].
template<bool INV>
__device__ __forceinline__ void reg_fft16(float2* v) {
    const float C[8] = { 1.f,  0.9238795325112867f,  0.7071067811865476f,  0.3826834323650898f,
                         0.f, -0.3826834323650898f, -0.7071067811865476f, -0.9238795325112867f};
    const float S[8] = { 0.f, -0.3826834323650898f, -0.7071067811865476f, -0.9238795325112867f,
                        -1.f, -0.9238795325112867f, -0.7071067811865476f, -0.3826834323650898f};
    #pragma unroll
    for (int m = 8; m >= 1; m >>= 1) {
        #pragma unroll
        for (int b = 0; b < 16; b += 2 * m) {
            #pragma unroll
            for (int i = 0; i < m; ++i) {
                float2 lo = v[b + i], hi = v[b + i + m];
                v[b + i] = make_float2(lo.x + hi.x, lo.y + hi.y);
                float2 d = make_float2(lo.x - hi.x, lo.y - hi.y);
                const int j = i * (8 / m);
                if (j == 0) {
                    v[b + i + m] = d;
                } else if (j == 4) {
                    v[b + i + m] = INV ? make_float2(-d.y, d.x)
                                       : make_float2( d.y, -d.x);
                } else {
                    float2 wt = make_float2(C[j], INV ? -S[j] : S[j]);
                    v[b + i + m] = cmul(d, wt);
                }
            }
        }
    }
}

// twiddle: v[slot holding k1=c] *= W_N^{+/- t*c}. Log-depth power groups.
template<bool INV>
__device__ __forceinline__ void twiddle16_nat(float2* v, int t, float twoPiOverN) {
    float ang = (INV ? twoPiOverN : -twoPiOverN) * (float)t;
    float2 w1; __sincosf(ang, &w1.y, &w1.x);
    float2 w2 = cmul(w1, w1);
    float2 w3 = cmul(w1, w2);
    float2 W4 = cmul(w2, w2);
    v[crev(1, 4)] = cmul(v[crev(1, 4)], w1);
    v[crev(2, 4)] = cmul(v[crev(2, 4)], w2);
    v[crev(3, 4)] = cmul(v[crev(3, 4)], w3);
    float2 Q = W4;
    #pragma unroll
    for (int g = 1; g < 4; ++g) {
        float2 q1 = cmul(Q, w1), q2 = cmul(Q, w2), q3 = cmul(Q, w3);
        v[crev(4 * g + 0, 4)] = cmul(v[crev(4 * g + 0, 4)], Q);
        v[crev(4 * g + 1, 4)] = cmul(v[crev(4 * g + 1, 4)], q1);
        v[crev(4 * g + 2, 4)] = cmul(v[crev(4 * g + 2, 4)], q2);
        v[crev(4 * g + 3, 4)] = cmul(v[crev(4 * g + 3, 4)], q3);
        if (g < 3) Q = cmul(Q, W4);
    }
}

// K1: rows. z = u + i*k (zero padded), FFT-512 (16reg x [16reg x 2-fold]),
// fp16 store into [seg][w][hL] -> 16KB fully contiguous per block.
__global__ void __launch_bounds__(256) fftconv_k1(const float* __restrict__ u,
                                                  const float* __restrict__ kk) {
    __shared__ __align__(16) float2 S[8][16][33];
    const int tid = threadIdx.x;
    const int lane = tid & 31, wid = tid >> 5;
    const int c = blockIdx.y;
    const int seg = blockIdx.x;
    const int h = seg * 8 + wid;

    float2 v[16];
    if (h < HH) {
        const float* pu = u + (size_t)(c * HH + h) * WW;
        const float* pk = kk + (size_t)(c * HH + h) * WW;
        #pragma unroll
        for (int s = 0; s < 16; ++s) {
            int n = lane + 32 * s;
            bool ok = n < WW;
            v[s].x = ok ? pu[n] : 0.f;
            v[s].y = ok ? pk[n] : 0.f;
        }
    } else {
        #pragma unroll
        for (int s = 0; s < 16; ++s) v[s] = make_float2(0.f, 0.f);
    }

    reg_fft16<false>(v);
    twiddle16_nat<false>(v, lane, 0.012271846303085130f);   // W512^{t*k1}
    #pragma unroll
    for (int r = 0; r < 16; ++r) S[wid][crev(r, 4)][lane] = v[r];
    __syncwarp();

    const int k1 = lane & 15, k2 = lane >> 4;
    {
        float2 q1; __sincosf(-0.19634954084936207f * (float)k2, &q1.y, &q1.x);
        float2 q2 = cmul(q1, q1);
        float2 q3 = cmul(q1, q2);
        float2 Q4 = cmul(q2, q2);
        float2 Qg = make_float2(1.f, 0.f);
        const float sgn = k2 ? -1.f : 1.f;
        #pragma unroll
        for (int g = 0; g < 4; ++g) {
            float2 t1 = cmul(Qg, q1), t2 = cmul(Qg, q2), t3 = cmul(Qg, q3);
            #pragma unroll
            for (int r = 0; r < 4; ++r) {
                int a = 4 * g + r;
                float2 L0 = S[wid][k1][a];
                float2 L1 = S[wid][k1][a + 16];
                float2 hh = make_float2(L0.x + sgn * L1.x, L0.y + sgn * L1.y);
                float2 wp_ = (r == 0) ? Qg : (r == 1) ? t1 : (r == 2) ? t2 : t3;
                v[a] = cmul(hh, wp_);
            }
            if (g < 3) Qg = cmul(Qg, Q4);
        }
    }
    reg_fft16<false>(v);                  // v[r] = X[lane + 32*crev(r)]
    __syncwarp();

    __half2* brow = (__half2*)&S[wid][0][0];
    #pragma unroll
    for (int r = 0; r < 16; ++r) {
        int k = lane + 32 * crev(r, 4);
        brow[k] = __floats2half2_rn(v[r].x, v[r].y);
    }
    __syncthreads();

    uint4* dst4 = (uint4*)(g_A + ((size_t)c * 32 + seg) * (512 * 8));
    #pragma unroll
    for (int q = 0; q < 4; ++q) {
        int li = tid + 256 * q;
        int w = li >> 1, part = li & 1;
        __half2 a0 = ((const __half2*)&S[part * 4 + 0][0][0])[w];
        __half2 a1 = ((const __half2*)&S[part * 4 + 1][0][0])[w];
        __half2 a2 = ((const __half2*)&S[part * 4 + 2][0][0])[w];
        __half2 a3 = ((const __half2*)&S[part * 4 + 3][0][0])[w];
        uint4 t;
        t.x = *reinterpret_cast<unsigned*>(&a0);
        t.y = *reinterpret_cast<unsigned*>(&a1);
        t.z = *reinterpret_cast<unsigned*>(&a2);
        t.w = *reinterpret_cast<unsigned*>(&a3);
        dst4[li] = t;
    }
}

// K2 v2: 16-thread group owns one column pair (w, 512-w). Phases:
// fwd FFT(mirror) -> Zmir to fp16 smem -> fwd FFT(low, in regs) -> product
// -> inverse FFT -> store low col. All threads active in every phase.
__global__ void __launch_bounds__(256) fftconv_k2() {
    extern __shared__ __align__(16) char SM[];
    __half2* stageL = (__half2*)SM;                 // [16][256] low cols / result
    __half2* stageM = (__half2*)(SM + 16384);       // [16][256] mirror cols / Zmir
    float2*  Tb     = (float2*)(SM + 32768);        // [16][272] transpose scratch
    const int tid = threadIdx.x;
    const int gi = tid >> 4, tl = tid & 15;
    const int c = 255 - blockIdx.y;       // reversed: read K1's youngest L2 lines
    const int w0 = blockIdx.x * 16;
    __half2* gch = g_A + (size_t)c * (32 * 512 * 8);

    // cooperative coalesced load: 16 low cols (clamped) + their mirrors
    for (int li = tid; li < 1024; li += 256) {
        int wi = li & 15, uu = li >> 4;   // uu = seg*2 + part
        int seg = uu >> 1, part = uu & 1;
        int colL = w0 + wi; if (colL > 256) colL = 256;   // clamp keeps groups convergent
        int colM = (512 - colL) & 511;
        const uint4* sL = (const uint4*)(gch + ((size_t)seg * 512 + colL) * 8);
        const uint4* sM = (const uint4*)(gch + ((size_t)seg * 512 + colM) * 8);
        ((uint4*)stageL)[wi * 64 + uu] = sL[part];
        ((uint4*)stageM)[wi * 64 + uu] = sM[part];
    }
    __syncthreads();

    float2* T = Tb + gi * 272;
    __half2* mslot = stageM + gi * 256;
    __half2* lslot = stageL + gi * 256;
    float2 v[16];

    // ---- forward FFT-256 of mirror column ----
    #pragma unroll
    for (int s = 0; s < 16; ++s) v[s] = __half22float2(mslot[tl + 16 * s]);
    __syncwarp();                         // mslot reads done before overwrite below
    reg_fft16<false>(v);
    twiddle16_nat<false>(v, tl, 0.024543692606170260f);
    #pragma unroll
    for (int r = 0; r < 16; ++r) T[crev(r, 4) * 17 + tl] = v[r];
    __syncwarp();
    #pragma unroll
    for (int j = 0; j < 16; ++j) v[j] = T[tl * 17 + j];
    reg_fft16<false>(v);                  // Zmir[tl + 16*crev(r)]
    #pragma unroll
    for (int r = 0; r < 16; ++r)          // Zmir natural-k, fp16, over dead slot
        mslot[tl + 16 * crev(r, 4)] = __floats2half2_rn(v[r].x, v[r].y);
    __syncwarp();                         // T reads done + Zmir visible in group

    // ---- forward FFT-256 of low column (Z stays in registers) ----
    #pragma unroll
    for (int s = 0; s < 16; ++s) v[s] = __half22float2(lslot[tl + 16 * s]);
    __syncwarp();                         // lslot reads done before result overwrite
    reg_fft16<false>(v);
    twiddle16_nat<false>(v, tl, 0.024543692606170260f);
    #pragma unroll
    for (int r = 0; r < 16; ++r) T[crev(r, 4) * 17 + tl] = v[r];
    __syncwarp();
    #pragma unroll
    for (int j = 0; j < 16; ++j) v[j] = T[tl * 17 + j];
    reg_fft16<false>(v);                  // Zlow[tl + 16*crev(r)]
    __syncwarp();                         // T reads done before inverse reuse

    // ---- Hermitian split + pointwise product, relabel bitrev -> natural ----
    float2 v2[16];
    #pragma unroll
    for (int r = 0; r < 16; ++r) {
        int k = tl + 16 * crev(r, 4);
        int km = (HP - k) & (HP - 1);
        float2 z1 = v[r];                 // Z(k, w)
        float2 z2 = __half22float2(mslot[km]);   // Z(-k, -w)
        float2 uf = make_float2(0.5f * (z1.x + z2.x),  0.5f * (z1.y - z2.y));
        float2 kf = make_float2(0.5f * (z1.y + z2.y), -0.5f * (z1.x - z2.x));
        v2[crev(r, 4)] = cmul(uf, kf);
    }

    // ---- inverse FFT-256 ----
    reg_fft16<true>(v2);
    twiddle16_nat<true>(v2, tl, 0.024543692606170260f);
    #pragma unroll
    for (int r = 0; r < 16; ++r) T[crev(r, 4) * 17 + tl] = v2[r];
    __syncwarp();
    #pragma unroll
    for (int j = 0; j < 16; ++j) v2[j] = T[tl * 17 + j];
    reg_fft16<true>(v2);                  // G[tl + 16*crev(r)]

    const float SC2 = 0.000244140625f;    // 2^-12 prescale (fp16 range)
    #pragma unroll
    for (int r = 0; r < 16; ++r)
        lslot[tl + 16 * crev(r, 4)] = __floats2half2_rn(v2[r].x * SC2, v2[r].y * SC2);
    __syncthreads();

    // cooperative coalesced store of valid low cols only
    for (int li = tid; li < 1024; li += 256) {
        int wi = li & 15, uu = li >> 4;
        int seg = uu >> 1, part = uu & 1;
        int colL = w0 + wi;
        if (colL <= 256) {
            uint4* d = (uint4*)(gch + ((size_t)seg * 512 + colL) * 8);
            d[part] = ((const uint4*)stageL)[wi * 64 + uu];
        }
    }
}

// K3: irfft rows. Load G(h, 0..256), pack Z[j]=E+iO (half-size trick),
// one complex IFFT-256 per row (16 threads/row), y[2n]=Re, y[2n+1]=Im.
__global__ void __launch_bounds__(256) fftconv_k3(float* __restrict__ y) {
    __shared__ __align__(16) char SM3[34816];
    __half2* Gs = (__half2*)SM3;          // [row g][w], stride 264 half2
    float2*  Tb = (float2*)SM3;           // [group][272] float2 (reused)
    const int tid = threadIdx.x;
    const int g = tid >> 4, tl = tid & 15;
    const int c = blockIdx.y;
    const int sp = blockIdx.x;
    const int h = sp * 16 + g;

    #pragma unroll
    for (int sl = 0; sl < 2; ++sl) {
        const uint4* src4 = (const uint4*)(g_A + ((size_t)c * 32 + 2 * sp + sl) * (512 * 8));
        for (int li = tid; li < 514; li += 256) {
            int w = li >> 1, part = li & 1;
            uint4 t = src4[li];
            int r0 = sl * 8 + part * 4;
            Gs[(r0 + 0) * 264 + w] = *reinterpret_cast<__half2*>(&t.x);
            Gs[(r0 + 1) * 264 + w] = *reinterpret_cast<__half2*>(&t.y);
            Gs[(r0 + 2) * 264 + w] = *reinterpret_cast<__half2*>(&t.z);
            Gs[(r0 + 3) * 264 + w] = *reinterpret_cast<__half2*>(&t.w);
        }
    }
    __syncthreads();

    const float Ct[16] = { 1.f,  0.980785280403230f,  0.923879532511287f,  0.831469612302545f,
                           0.707106781186548f,  0.555570233019602f,  0.382683432365090f,  0.195090322016128f,
                           0.f, -0.195090322016128f, -0.382683432365090f, -0.555570233019602f,
                          -0.707106781186548f, -0.831469612302545f, -0.923879532511287f, -0.980785280403230f};
    const float St[16] = { 0.f,  0.195090322016128f,  0.382683432365090f,  0.555570233019602f,
                           0.707106781186548f,  0.831469612302545f,  0.923879532511287f,  0.980785280403230f,
                           1.f,  0.980785280403230f,  0.923879532511287f,  0.831469612302545f,
                           0.707106781186548f,  0.555570233019602f,  0.382683432365090f,  0.195090322016128f};
    float2 base;                           // e^{+2pi i tl/512}
    __sincosf(0.012271846303085130f * (float)tl, &base.y, &base.x);

    float2 v[16];
    const __half2* grow = Gs + g * 264;
    #pragma unroll
    for (int cc = 0; cc < 16; ++cc) {
        int j = tl + 16 * cc;
        float2 Gj = __half22float2(grow[j]);
        float2 Gm = __half22float2(grow[256 - j]);
        float2 A = make_float2(Gj.x + Gm.x, Gj.y - Gm.y);
        float2 D = make_float2(Gj.x - Gm.x, Gj.y + Gm.y);
        float2 tw = cmul(base, make_float2(Ct[cc], St[cc]));
        float2 P = cmul(tw, D);
        v[cc] = make_float2(A.x - P.y, A.y + P.x);
    }
    __syncthreads();                       // Gs dead; Tb live

    reg_fft16<true>(v);
    twiddle16_nat<true>(v, tl, 0.024543692606170260f);
    float2* T = Tb + g * 272;
    #pragma unroll
    for (int r = 0; r < 16; ++r) T[crev(r, 4) * 17 + tl] = v[r];
    __syncwarp();
    #pragma unroll
    for (int j = 0; j < 16; ++j) v[j] = T[tl * 17 + j];
    reg_fft16<true>(v);

    if (h < HH) {
        const float s = 8.6316745750903e-05f;   // 2^-13.5
        float* py = y + (size_t)(c * HH + h) * WW;
        #pragma unroll
        for (int r = 0; r < 16; ++r) {
            int m = tl + 16 * crev(r, 4);
            if (m <= 253) {
                py[2 * m]     = v[r].x * s;
                py[2 * m + 1] = v[r].y * s;
            } else if (m == 254) {
                py[508] = v[r].x * s;
            }
        }
    }
}

extern "C" void kernel_launch(void* const* d_in, const int* in_sizes, int n_in,
                              void* d_out, int out_size) {
    const float* u = (const float*)d_in[0];
    const float* k = (const float*)d_in[1];
    float* y = (float*)d_out;

    static const int K2_SMEM = 16384 + 16384 + 16 * 272 * 8;   // 67584 B
    cudaFuncSetAttribute(fftconv_k2, cudaFuncAttributeMaxDynamicSharedMemorySize, K2_SMEM);

    fftconv_k1<<<dim3(32, CH), 256>>>(u, k);          // seg 0..31 per channel
    fftconv_k2<<<dim3(17, CH), 256, K2_SMEM>>>();     // 16 pairs per block
    fftconv_k3<<<dim3(16, CH), 256>>>(y);             // 16 rows (2 segs) per block
}